// round 5
// baseline (speedup 1.0000x reference)
#include <cuda_runtime.h>
#include <math.h>

#define BB 4096
#define IN_DIM 64
#define UU 256
#define NN 128
#define WW 64
#define OUT_DIM 64
#define NPH 70
#define PDIM 268   // 2*NPH + 2*W
#define CLIPV 20.0f
#define EPSV 1e-12f

// d_out layout (reference tuple order, each flattened):
#define O_OUT 0
#define O_RV  (BB*OUT_DIM)                 // 262144
#define O_WR  (O_RV + BB*WW)               // 524288
#define O_WW  (O_WR + BB*NN)               // 1048576
#define O_M   (O_WW + BB*NN)               // 1572864
#define O_H   (O_M + (size_t)BB*NN*WW)     // 35127296
#define O_C   (O_H + (size_t)BB*UU)        // 36175872

__device__ float g_params[BB * PDIM];      // scratch: clipped head params

__device__ __forceinline__ float sigf(float x) { return 1.0f / (1.0f + expf(-x)); }
__device__ __forceinline__ float softplusf(float x) { return log1pf(expf(x)); }
__device__ __forceinline__ float clipf(float x) { return fminf(fmaxf(x, -CLIPV), CLIPV); }

// ---------------------------------------------------------------------------
// K1: z = [x,rv0]@W_k + h0@W_r + b ; LSTM gate epilogue -> h_new, c_new
// grid (64, 4): blockIdx.x = 64-row tile, blockIdx.y = 64-wide u group.
// Each CTA computes all 4 gates for its (64 rows x 64 u) tile.
// ---------------------------------------------------------------------------
__global__ __launch_bounds__(256) void k1_lstm(
    const float* __restrict__ x, const float* __restrict__ rv0,
    const float* __restrict__ h0, const float* __restrict__ c0,
    const float* __restrict__ Wk, const float* __restrict__ Wr,
    const float* __restrict__ bl, float* __restrict__ out)
{
    __shared__ float As[32][65];       // [k][row]
    __shared__ float Ws[32 * 256];     // [k][g*64+uc]
    int tid = threadIdx.x;
    int uc = tid & 63, ty = tid >> 6;
    int row0 = blockIdx.x * 64;
    int u0 = blockIdx.y * 64;

    float acc[4][16];
#pragma unroll
    for (int g = 0; g < 4; g++)
#pragma unroll
        for (int j = 0; j < 16; j++) acc[g][j] = 0.0f;

    for (int kb = 0; kb < 384; kb += 32) {
        // stage A tile (64 rows x 32 k), coalesced over k
        {
            int kl = tid & 31, rr = tid >> 5;
#pragma unroll
            for (int p = 0; p < 8; p++) {
                int row = rr + p * 8;
                int kg = kb + kl;
                float v;
                if (kg < 64)        v = x[(row0 + row) * 64 + kg];
                else if (kg < 128)  v = rv0[(row0 + row) * 64 + (kg - 64)];
                else                v = h0[(row0 + row) * 256 + (kg - 128)];
                As[kl][row] = v;
            }
        }
        // stage W tile (32 k x 256 cols = 4 gates x 64 u), coalesced over cols
#pragma unroll
        for (int i = 0; i < 32; i++) {
            int idx = tid + i * 256;
            int kl = idx >> 8;
            int cl = idx & 255;               // g*64 + u
            int g = cl >> 6, u = cl & 63;
            int colg = g * 256 + u0 + u;
            int kg = kb + kl;
            float v = (kg < 128) ? Wk[kg * 1024 + colg]
                                 : Wr[(kg - 128) * 1024 + colg];
            Ws[kl * 256 + cl] = v;
        }
        __syncthreads();
#pragma unroll
        for (int k = 0; k < 32; k++) {
            float a[16];
#pragma unroll
            for (int j = 0; j < 16; j++) a[j] = As[k][ty * 16 + j];
#pragma unroll
            for (int g = 0; g < 4; g++) {
                float w = Ws[k * 256 + g * 64 + uc];
#pragma unroll
                for (int j = 0; j < 16; j++) acc[g][j] += a[j] * w;
            }
        }
        __syncthreads();
    }

    int u = u0 + uc;
    float bi = bl[0 * 256 + u], bf = bl[1 * 256 + u];
    float bg = bl[2 * 256 + u], bo = bl[3 * 256 + u];
#pragma unroll
    for (int j = 0; j < 16; j++) {
        int row = row0 + ty * 16 + j;
        float zi = acc[0][j] + bi;
        float zf = acc[1][j] + bf;
        float zg = acc[2][j] + bg;
        float zo = acc[3][j] + bo;
        float cn = sigf(zf) * c0[row * 256 + u] + sigf(zi) * tanhf(zg);
        float hn = sigf(zo) * tanhf(cn);
        out[O_H + (size_t)row * 256 + u] = hn;
        out[O_C + (size_t)row * 256 + u] = cn;
    }
}

// ---------------------------------------------------------------------------
// K2: params = clip(h_new @ W_p + b_p).  16 rows per CTA, 1 thread per col.
// ---------------------------------------------------------------------------
__global__ __launch_bounds__(288) void k2_params(
    const float* __restrict__ out /* d_out base */,
    const float* __restrict__ Wp, const float* __restrict__ bp)
{
    __shared__ float hs[16 * 256];
    int row0 = blockIdx.x * 16;
    for (int i = threadIdx.x; i < 16 * 256; i += 288) {
        int r = i >> 8, k = i & 255;
        hs[i] = out[O_H + (size_t)(row0 + r) * 256 + k];
    }
    __syncthreads();
    int c = threadIdx.x;
    if (c < PDIM) {
        float acc[16];
#pragma unroll
        for (int j = 0; j < 16; j++) acc[j] = 0.0f;
#pragma unroll 4
        for (int k = 0; k < 256; k++) {
            float w = Wp[k * PDIM + c];
#pragma unroll
            for (int j = 0; j < 16; j++) acc[j] += hs[j * 256 + k] * w;
        }
        float b = bp[c];
#pragma unroll
        for (int j = 0; j < 16; j++)
            g_params[(row0 + j) * PDIM + c] = clipf(acc[j] + b);
    }
}

// ---------------------------------------------------------------------------
// K3: per-sample addressing (2 heads) + read_vec + memory update.
// One CTA per sample, 128 threads (one per memory slot n).
// ---------------------------------------------------------------------------
__global__ __launch_bounds__(128) void k3_addr(
    const float* __restrict__ M,
    const float* __restrict__ w0p, const float* __restrict__ w1p,
    float* __restrict__ out)
{
    __shared__ float Ms[128 * 65];   // [n][w], stride 65: conflict-free both ways
    __shared__ float psm[PDIM];
    __shared__ float ks[64], er[64], ad[64];
    __shared__ float wgs[128], wrs[128], wws[128];
    __shared__ float red[4];
    __shared__ float part[128];

    int b = blockIdx.x, tid = threadIdx.x;
    int lane = tid & 31, wid = tid >> 5;

    // stage M (float4 global loads, scalar smem stores due to stride-65)
    const float4* M4 = (const float4*)(M + (size_t)b * NN * WW);
#pragma unroll
    for (int t = 0; t < 16; t++) {
        int idx4 = tid + t * 128;
        float4 v = M4[idx4];
        int n = idx4 >> 4, w0 = (idx4 & 15) * 4;
        float* p = &Ms[n * 65 + w0];
        p[0] = v.x; p[1] = v.y; p[2] = v.z; p[3] = v.w;
    }
    for (int i = tid; i < PDIM; i += 128) psm[i] = g_params[b * PDIM + i];
    __syncthreads();

    // per-row inverse norms of M (thread n owns row n)
    float s = 0.0f;
#pragma unroll
    for (int w = 0; w < 64; w++) { float m = Ms[tid * 65 + w]; s += m * m; }
    float minv = rsqrtf(fmaxf(s, EPSV));

    if (tid < 64) {
        er[tid] = sigf(psm[2 * NPH + tid]);
        ad[tid] = tanhf(psm[2 * NPH + WW + tid]);
    }

    for (int h = 0; h < 2; h++) {
        int off = h * NPH;
        if (tid < 64) ks[tid] = tanhf(psm[off + tid]);
        __syncthreads();

        // scalars (computed redundantly by all threads — cheap)
        float sk = 0.0f;
#pragma unroll
        for (int w = 0; w < 64; w++) sk += ks[w] * ks[w];
        float kninv = rsqrtf(fmaxf(sk, EPSV));
        float beta = softplusf(psm[off + 64]);
        float g = sigf(psm[off + 65]);
        float e0 = psm[off + 66], e1 = psm[off + 67], e2 = psm[off + 68];
        float mx3 = fmaxf(e0, fmaxf(e1, e2));
        float x0 = expf(e0 - mx3), x1 = expf(e1 - mx3), x2 = expf(e2 - mx3);
        float sinv = 1.0f / (x0 + x1 + x2);
        float s0 = x0 * sinv, s1 = x1 * sinv, s2 = x2 * sinv;
        float gamma = softplusf(psm[off + 69]) + 1.0f;

        // content similarity + softmax over n
        float dot = 0.0f;
#pragma unroll
        for (int w = 0; w < 64; w++) dot += ks[w] * Ms[tid * 65 + w];
        float v = beta * (-dot * kninv * minv);

        float m = v;
#pragma unroll
        for (int o = 16; o; o >>= 1) m = fmaxf(m, __shfl_xor_sync(0xffffffffu, m, o));
        if (lane == 0) red[wid] = m;
        __syncthreads();
        m = fmaxf(fmaxf(red[0], red[1]), fmaxf(red[2], red[3]));
        float e = expf(v - m);
        float ssum = e;
#pragma unroll
        for (int o = 16; o; o >>= 1) ssum += __shfl_xor_sync(0xffffffffu, ssum, o);
        __syncthreads();
        if (lane == 0) red[wid] = ssum;
        __syncthreads();
        ssum = red[0] + red[1] + red[2] + red[3];
        float wc = e / ssum;

        const float* prev = h ? w1p : w0p;
        float wg = g * wc + (1.0f - g) * prev[b * 128 + tid];
        wgs[tid] = wg;
        __syncthreads();

        // circular 3-tap shift, sharpen, renormalize
        float w_ = s0 * wg + s1 * wgs[(tid + 127) & 127] + s2 * wgs[(tid + 1) & 127];
        float wsh = powf(w_, gamma);
        float s2sum = wsh;
#pragma unroll
        for (int o = 16; o; o >>= 1) s2sum += __shfl_xor_sync(0xffffffffu, s2sum, o);
        __syncthreads();
        if (lane == 0) red[wid] = s2sum;
        __syncthreads();
        s2sum = red[0] + red[1] + red[2] + red[3];
        float wf = wsh / s2sum;

        if (h == 0) { wrs[tid] = wf; out[O_WR + (size_t)b * 128 + tid] = wf; }
        else        { wws[tid] = wf; out[O_WW + (size_t)b * 128 + tid] = wf; }
        __syncthreads();   // before next head overwrites ks/wgs/red
    }

    // read_vec[w] = sum_n wrs[n] * M[n][w]  (split over 2 halves of n)
    {
        int w = tid & 63, half = tid >> 6;
        float r = 0.0f;
#pragma unroll
        for (int i = 0; i < 64; i++) {
            int n = half * 64 + i;
            r += wrs[n] * Ms[n * 65 + w];
        }
        part[half * 64 + w] = r;
        __syncthreads();
        if (tid < 64) out[O_RV + (size_t)b * 64 + tid] = part[tid] + part[64 + tid];
    }

    // M_new = M*(1 - w_write*erase) + w_write*add, float4 coalesced writes
    float4* Mo = (float4*)(out + O_M + (size_t)b * NN * WW);
#pragma unroll
    for (int t = 0; t < 16; t++) {
        int idx4 = tid + t * 128;
        int n = idx4 >> 4, w0 = (idx4 & 15) * 4;
        float wn = wws[n];
        const float* p = &Ms[n * 65 + w0];
        float4 v;
        v.x = p[0] * (1.0f - wn * er[w0 + 0]) + wn * ad[w0 + 0];
        v.y = p[1] * (1.0f - wn * er[w0 + 1]) + wn * ad[w0 + 1];
        v.z = p[2] * (1.0f - wn * er[w0 + 2]) + wn * ad[w0 + 2];
        v.w = p[3] * (1.0f - wn * er[w0 + 3]) + wn * ad[w0 + 3];
        Mo[idx4] = v;
    }
}

// ---------------------------------------------------------------------------
// K4: out = clip([h_new, read_vec] @ W_o + b_o). 4 rows per CTA.
// ---------------------------------------------------------------------------
__global__ __launch_bounds__(256) void k4_out(
    const float* __restrict__ Wo, const float* __restrict__ bo,
    float* __restrict__ out)
{
    __shared__ float hs[4 * 320];
    int row0 = blockIdx.x * 4;
    for (int i = threadIdx.x; i < 4 * 320; i += 256) {
        int r = i / 320, k = i - r * 320;
        hs[i] = (k < 256) ? out[O_H + (size_t)(row0 + r) * 256 + k]
                          : out[O_RV + (size_t)(row0 + r) * 64 + (k - 256)];
    }
    __syncthreads();
    int r = threadIdx.x >> 6, c = threadIdx.x & 63;
    float acc = 0.0f;
#pragma unroll 4
    for (int k = 0; k < 320; k++) acc += hs[r * 320 + k] * Wo[k * 64 + c];
    acc = clipf(acc + bo[c]);
    out[O_OUT + (size_t)(row0 + r) * 64 + c] = acc;
}

// ---------------------------------------------------------------------------
extern "C" void kernel_launch(void* const* d_in, const int* in_sizes, int n_in,
                              void* d_out, int out_size)
{
    const float* x   = (const float*)d_in[0];
    const float* h0  = (const float*)d_in[1];
    const float* c0  = (const float*)d_in[2];
    const float* rv0 = (const float*)d_in[3];
    const float* w0p = (const float*)d_in[4];
    const float* w1p = (const float*)d_in[5];
    const float* M   = (const float*)d_in[6];
    const float* Wk  = (const float*)d_in[7];
    const float* Wr  = (const float*)d_in[8];
    const float* bl  = (const float*)d_in[9];
    const float* Wp  = (const float*)d_in[10];
    const float* bp  = (const float*)d_in[11];
    const float* Wo  = (const float*)d_in[12];
    const float* bo  = (const float*)d_in[13];
    float* out = (float*)d_out;

    dim3 g1(BB / 64, 4);
    k1_lstm<<<g1, 256>>>(x, rv0, h0, c0, Wk, Wr, bl, out);
    k2_params<<<BB / 16, 288>>>(out, Wp, bp);
    k3_addr<<<BB, 128>>>(M, w0p, w1p, out);
    k4_out<<<BB / 4, 256>>>(Wo, bo, out);
}